// round 9
// baseline (speedup 1.0000x reference)
#include <cuda_runtime.h>
#include <cstdint>

#define L 1024
#define D 64
#define NBH 64
#define OUT_ELEMS (NBH*L*D)
#define SQ 68   // padded row stride (floats) for Q smem

__device__ float g_inv_l[NBH * L];   // per-row 1/sum(exp(s)), qk -> pv

__device__ __forceinline__ uint32_t f2tf(float x) {
    uint32_t r; asm("cvt.rna.tf32.f32 %0, %1;" : "=r"(r) : "f"(x)); return r;
}

__device__ __forceinline__ void mma_tf32(float* c,
    uint32_t a0, uint32_t a1, uint32_t a2, uint32_t a3, uint32_t b0, uint32_t b1)
{
    asm("mma.sync.aligned.m16n8k8.row.col.f32.tf32.tf32.f32 "
        "{%0,%1,%2,%3}, {%4,%5,%6,%7}, {%8,%9}, {%0,%1,%2,%3};"
        : "+f"(c[0]), "+f"(c[1]), "+f"(c[2]), "+f"(c[3])
        : "r"(a0), "r"(a1), "r"(a2), "r"(a3), "r"(b0), "r"(b1));
}

// ---------------------------------------------------------------------------
// Kernel 1: per (qt, bh) strip of 128 x 1024.
// e = exp(QK^T/8 masked + bias) -> score buffer (holds exp!), and
// g_inv_l = 1 / row-sum(e).  3xTF32 split MMA.
// Q: raw padded rows in smem, split to tf32 hi/lo per kk in registers.
// K: pre-split fragment uint4 {hi(t),hi(t+4),lo(t),lo(t+4)} at
//    KB[row*32 + ((kk^row)&7)*4 + t]  (XOR swizzle + store rotation:
//    both LDS.128 read and STS.128 write run at the 4-phase floor).
// ---------------------------------------------------------------------------
__global__ __launch_bounds__(256, 2)
void qks_kernel(const float* __restrict__ Q, const float* __restrict__ K,
                const int* __restrict__ mask, const float* __restrict__ bias,
                float* __restrict__ score)
{
    extern __shared__ float sm[];
    float* Qs   = sm;                          // 128 x 68 floats (34816 B)
    uint4* KB   = (uint4*)(sm + 128 * SQ);     // 4096 uint4 (65536 B)
    float* sred = sm + 128 * SQ + 16384;       // 256 floats

    const int tid  = threadIdx.x;
    const int lane = tid & 31, wid = tid >> 5;
    const int wq = wid & 3, wk = wid >> 2;
    const int g = lane >> 2, t = lane & 3;
    const int qt = blockIdx.x, bh = blockIdx.y;
    const int b = bh >> 4, h = bh & 15;

    // ---- Q tile once, raw padded rows ----
    {
        const float4* Qg = (const float4*)(Q + ((size_t)bh * L + qt * 128) * D);
        #pragma unroll
        for (int it = 0; it < 8; it++) {
            int i = tid + it * 256; int r = i >> 4, dq = i & 15;
            ((float4*)(Qs + r * SQ))[dq] = Qg[r * 16 + dq];
        }
    }

    const int krow = tid >> 1, kh = tid & 1;
    const int rot  = (krow >> 1) & 3;

    float l_run[4] = {0.f, 0.f, 0.f, 0.f};

    for (int kt = 0; kt < 8; kt++) {
        __syncthreads();
        // ---- K tile: load, split hi/lo, store fragment uint4 ----
        {
            const float4* Kg = (const float4*)(K + ((size_t)bh * L + kt * 128) * D);
            #pragma unroll
            for (int i = 0; i < 4; i++) {
                int kk = kh * 4 + i;
                float4 v0 = Kg[krow * 16 + kk * 2];
                float4 v1 = Kg[krow * 16 + kk * 2 + 1];
                float f[8] = {v0.x, v0.y, v0.z, v0.w, v1.x, v1.y, v1.z, v1.w};
                uint32_t hi[8], lo[8];
                #pragma unroll
                for (int j = 0; j < 8; j++) {
                    hi[j] = f2tf(f[j]);
                    lo[j] = f2tf(f[j] - __uint_as_float(hi[j]));
                }
                uint4* dst = KB + krow * 32 + ((kk ^ krow) & 7) * 4;
                #pragma unroll
                for (int j = 0; j < 4; j++) {
                    int tt = (j + rot) & 3;
                    dst[tt] = make_uint4(hi[tt], hi[tt + 4], lo[tt], lo[tt + 4]);
                }
            }
        }
        __syncthreads();

        float acc[2][8][4];
        #pragma unroll
        for (int mt = 0; mt < 2; mt++)
            #pragma unroll
            for (int nt = 0; nt < 8; nt++)
                #pragma unroll
                for (int r = 0; r < 4; r++) acc[mt][nt][r] = 0.f;

        const float* Qw = Qs + (wq * 32) * SQ;

        #pragma unroll
        for (int kk = 0; kk < 8; kk++) {
            uint32_t ahi[2][4], alo[2][4];
            #pragma unroll
            for (int mt = 0; mt < 2; mt++)
                #pragma unroll
                for (int r = 0; r < 4; r++) {
                    int row = mt * 16 + g + (r & 1) * 8;
                    int col = kk * 8 + t + (r >> 1) * 4;
                    float x = Qw[row * SQ + col];
                    uint32_t hi = f2tf(x);
                    ahi[mt][r] = hi;
                    alo[mt][r] = f2tf(x - __uint_as_float(hi));
                }
            #pragma unroll
            for (int nt = 0; nt < 8; nt++) {
                int n = wk * 64 + nt * 8 + g;
                uint4 bb = KB[n * 32 + ((kk ^ n) & 7) * 4 + t];
                #pragma unroll
                for (int mt = 0; mt < 2; mt++) {
                    mma_tf32(acc[mt][nt], ahi[mt][0], ahi[mt][1], ahi[mt][2], ahi[mt][3], bb.z, bb.w);
                    mma_tf32(acc[mt][nt], alo[mt][0], alo[mt][1], alo[mt][2], alo[mt][3], bb.x, bb.y);
                    mma_tf32(acc[mt][nt], ahi[mt][0], ahi[mt][1], ahi[mt][2], ahi[mt][3], bb.x, bb.y);
                }
            }
        }

        // ---- epilogue: scale, mask, bias, store e=exp(s), accumulate l ----
        const int q0 = qt * 128 + wq * 32;
        const int cp0 = kt * 64 + wk * 32;   // float2 col-index base
        #pragma unroll
        for (int mt = 0; mt < 2; mt++)
            #pragma unroll
            for (int half = 0; half < 2; half++) {
                int row = q0 + mt * 16 + half * 8 + g;
                const int2*   mrow = (const int2*)  (mask  + ((size_t)b  * L + row) * L);
                const float2* brow = (const float2*)(bias  + ((size_t)h  * L + row) * L);
                float2*       srow = (float2*)      (score + ((size_t)bh * L + row) * L);
                float lsum = 0.f;
                #pragma unroll
                for (int nt = 0; nt < 8; nt++) {
                    int cp = cp0 + nt * 4 + t;
                    int2   mv = mrow[cp];
                    float2 bv = brow[cp];
                    float s0 = acc[mt][nt][half * 2 + 0] * 0.125f;
                    float s1 = acc[mt][nt][half * 2 + 1] * 0.125f;
                    s0 = (mv.x == 0 ? -10000.f : s0) + bv.x;
                    s1 = (mv.y == 0 ? -10000.f : s1) + bv.y;
                    float e0 = __expf(s0), e1 = __expf(s1);
                    srow[cp] = make_float2(e0, e1);
                    lsum += e0 + e1;
                }
                l_run[mt * 2 + half] += lsum;
            }
    }

    #pragma unroll
    for (int li = 0; li < 4; li++) {
        l_run[li] += __shfl_xor_sync(0xffffffffu, l_run[li], 1);
        l_run[li] += __shfl_xor_sync(0xffffffffu, l_run[li], 2);
    }
    __syncthreads();
    if (t == 0) {
        #pragma unroll
        for (int li = 0; li < 4; li++) {
            int row = wq * 32 + (li >> 1) * 16 + (li & 1) * 8 + g;
            sred[wk * 128 + row] = l_run[li];
        }
    }
    __syncthreads();
    if (tid < 128) {
        float l = sred[tid] + sred[128 + tid];
        g_inv_l[(size_t)bh * L + qt * 128 + tid] = 1.0f / l;
    }
}

// ---------------------------------------------------------------------------
// Kernel 2: O = P V with P = e * inv_l; writes normalized p over e in score.
// P fragments: uint2 {tf(p_t), tf(p_t+4)} at AF[row*34 + kk*4 + t]
//   (stride 34 -> bank = 4(row&7)+2t: exactly 2 lanes/bank-pair = LDS.64 floor;
//    writer rotates store order by (j+row+2h)&3 -> conflict-free STS.64).
// V fragments: uint2 with ^((nt&3)<<2) lane swizzle.
// Register-staged software pipeline over 16 k-chunks of 64.
// ---------------------------------------------------------------------------
struct Stage { float4 se[8]; float4 sv[4]; };

__device__ __forceinline__ void load_stage(Stage& st, const float* sbase,
                                           const float4* Vg, int c, int tid)
{
    const int prow = tid >> 1, h = tid & 1;
    #pragma unroll
    for (int i = 0; i < 4; i++)
        #pragma unroll
        for (int w = 0; w < 2; w++)
            st.se[i * 2 + w] = *(const float4*)(sbase + (size_t)prow * L + c * 64
                                                + (h * 4 + i) * 8 + w * 4);
    const int vrow = tid >> 2;
    #pragma unroll
    for (int it = 0; it < 4; it++) {
        int qd = (tid & 3) + it * 4;
        st.sv[it] = Vg[(size_t)(c * 64 + vrow) * 16 + qd];
    }
}

__global__ __launch_bounds__(256, 2)
void pv_kernel(const float* __restrict__ V, float* score, float* __restrict__ out)
{
    extern __shared__ uint32_t smu[];
    uint2*    AF   = (uint2*)smu;                 // 4352 uint2 (34816 B)
    uint2*    VF   = (uint2*)(smu + 4352 * 2);    // 2048 uint2 (16384 B)
    uint32_t* VFw  = (uint32_t*)VF;
    float*    sinv = (float*)(smu + (4352 + 2048) * 2);   // 128 floats

    const int tid  = threadIdx.x;
    const int lane = tid & 31, wid = tid >> 5;
    const int g = lane >> 2, t = lane & 3;
    const int qt = blockIdx.x, bh = blockIdx.y;

    const float4* Vg    = (const float4*)(V + (size_t)bh * L * D);
    float*        sbase = score + ((size_t)bh * L + qt * 128) * L;

    Stage st;
    load_stage(st, sbase, Vg, 0, tid);
    if (tid < 128) sinv[tid] = g_inv_l[(size_t)bh * L + qt * 128 + tid];
    __syncthreads();
    const float il = sinv[tid >> 1];

    float acc[8][4];
    #pragma unroll
    for (int nt = 0; nt < 8; nt++)
        #pragma unroll
        for (int r = 0; r < 4; r++) acc[nt][r] = 0.f;

    const int prow = tid >> 1, h = tid & 1;
    const int vrow = tid >> 2;
    const int vkk = vrow >> 3, ts = vrow & 7, vword = ts >> 2, vt = ts & 3;

    for (int c = 0; c < 16; c++) {
        __syncthreads();   // previous MMA done reading smem
        // ---- transform: p = e*il -> gmem (standard layout) + fragment smem ----
        #pragma unroll
        for (int i = 0; i < 4; i++) {
            int kk = h * 4 + i;
            float p[8];
            #pragma unroll
            for (int w = 0; w < 2; w++) {
                const float4& e4 = st.se[i * 2 + w];
                p[w * 4 + 0] = e4.x * il; p[w * 4 + 1] = e4.y * il;
                p[w * 4 + 2] = e4.z * il; p[w * 4 + 3] = e4.w * il;
            }
            float* gdst = sbase + (size_t)prow * L + c * 64 + kk * 8;
            *(float4*)gdst       = make_float4(p[0], p[1], p[2], p[3]);
            *(float4*)(gdst + 4) = make_float4(p[4], p[5], p[6], p[7]);
            uint32_t tf[8];
            #pragma unroll
            for (int j = 0; j < 8; j++) tf[j] = f2tf(p[j]);
            uint2* dst = AF + prow * 34 + kk * 4;
            #pragma unroll
            for (int j = 0; j < 4; j++) {
                int tt = (j + prow + 2 * h) & 3;
                dst[tt] = make_uint2(tf[tt], tf[tt + 4]);
            }
        }
        // ---- V fragments ----
        #pragma unroll
        for (int it = 0; it < 4; it++) {
            int qd = (tid & 3) + it * 4;
            #pragma unroll
            for (int j = 0; j < 4; j++) {
                int n = qd * 4 + j;
                int nt = n >> 3, gn = n & 7;
                int slot = (gn * 4 + vt) ^ ((nt & 3) << 2);
                VFw[((vkk * 8 + nt) * 32 + slot) * 2 + vword] = f2tf((&st.sv[it].x)[j]);
            }
        }
        __syncthreads();

        if (c < 15) load_stage(st, sbase, Vg, c + 1, tid);   // overlap with MMA

        const int arow0 = wid * 16 + g;
        #pragma unroll
        for (int kk = 0; kk < 8; kk++) {
            uint2 u0 = AF[arow0 * 34 + kk * 4 + t];
            uint2 u1 = AF[(arow0 + 8) * 34 + kk * 4 + t];
            #pragma unroll
            for (int nt = 0; nt < 8; nt++) {
                uint2 bb = VF[(kk * 8 + nt) * 32 + (lane ^ ((nt & 3) << 2))];
                mma_tf32(acc[nt], u0.x, u1.x, u0.y, u1.y, bb.x, bb.y);
            }
        }
    }

    #pragma unroll
    for (int half = 0; half < 2; half++) {
        int row = qt * 128 + wid * 16 + half * 8 + g;
        float2* orow = (float2*)(out + ((size_t)bh * L + row) * D);
        #pragma unroll
        for (int nt = 0; nt < 8; nt++)
            orow[nt * 4 + t] = make_float2(acc[nt][half * 2], acc[nt][half * 2 + 1]);
    }
}

// ---------------------------------------------------------------------------
extern "C" void kernel_launch(void* const* d_in, const int* in_sizes, int n_in,
                              void* d_out, int out_size)
{
    const float* Q    = (const float*)d_in[0];
    const float* K    = (const float*)d_in[1];
    const float* V    = (const float*)d_in[2];
    const int*   mask = (const int*)  d_in[3];
    const float* bias = (const float*)d_in[4];

    float* out   = (float*)d_out;
    float* score = out + OUT_ELEMS;   // tuple order: (out, score)

    const int qk_smem = 128 * SQ * 4 + 65536 + 1024;          // 101376 B
    const int pv_smem = (4352 + 2048) * 8 + 512;              // 51712 B
    cudaFuncSetAttribute(qks_kernel, cudaFuncAttributeMaxDynamicSharedMemorySize, qk_smem);
    cudaFuncSetAttribute(pv_kernel,  cudaFuncAttributeMaxDynamicSharedMemorySize, pv_smem);

    qks_kernel<<<dim3(8, 64), 256, qk_smem>>>(Q, K, mask, bias, score);
    pv_kernel <<<dim3(8, 64), 256, pv_smem>>>(V, score, out);
}

// round 11
// speedup vs baseline: 1.2785x; 1.2785x over previous
#include <cuda_runtime.h>
#include <cstdint>

#define L 1024
#define D 64
#define NBH 64
#define OUT_ELEMS (NBH*L*D)
#define SQ 68   // padded row stride (floats) for Q/K smem

__device__ float g_inv_l[NBH * L];   // per-row 1/sum(exp(s)), qk -> pv

__device__ __forceinline__ uint32_t f2tf(float x) {
    uint32_t r; asm("cvt.rna.tf32.f32 %0, %1;" : "=r"(r) : "f"(x)); return r;
}

__device__ __forceinline__ void mma_tf32(float* c,
    uint32_t a0, uint32_t a1, uint32_t a2, uint32_t a3, uint32_t b0, uint32_t b1)
{
    asm("mma.sync.aligned.m16n8k8.row.col.f32.tf32.tf32.f32 "
        "{%0,%1,%2,%3}, {%4,%5,%6,%7}, {%8,%9}, {%0,%1,%2,%3};"
        : "+f"(c[0]), "+f"(c[1]), "+f"(c[2]), "+f"(c[3])
        : "r"(a0), "r"(a1), "r"(a2), "r"(a3), "r"(b0), "r"(b1));
}

__device__ __forceinline__ void cp16(float* smem_dst, const float* gsrc) {
    uint32_t s = (uint32_t)__cvta_generic_to_shared(smem_dst);
    asm volatile("cp.async.cg.shared.global [%0], [%1], 16;" :: "r"(s), "l"(gsrc));
}
__device__ __forceinline__ void cp_commit() {
    asm volatile("cp.async.commit_group;");
}
template<int N> __device__ __forceinline__ void cp_wait() {
    asm volatile("cp.async.wait_group %0;" :: "n"(N));
}

// ---------------------------------------------------------------------------
// Kernel 1: per (qt, bh) strip of 128 x 1024.
// e = exp(QK^T/8 masked + bias) -> score buffer (holds exp!), and
// g_inv_l = 1 / row-sum(e).  3xTF32 split MMA.
// R3 structure (raw padded rows, in-loop hi/lo split) + cp.async
// double-buffered K tiles to overlap the K LDG with MMA+epilogue.
// ---------------------------------------------------------------------------
__global__ __launch_bounds__(256, 2)
void qks_kernel(const float* __restrict__ Q, const float* __restrict__ K,
                const int* __restrict__ mask, const float* __restrict__ bias,
                float* __restrict__ score)
{
    extern __shared__ float sm[];
    float* Qs   = sm;                    // 128 x 68
    float* Ksb  = sm + 128 * SQ;         // 2 x (128 x 68) double buffer
    float* sred = sm + 3 * 128 * SQ;     // 256 floats

    const int tid  = threadIdx.x;
    const int lane = tid & 31, wid = tid >> 5;
    const int wq = wid & 3, wk = wid >> 2;
    const int g = lane >> 2, t = lane & 3;
    const int qt = blockIdx.x, bh = blockIdx.y;
    const int b = bh >> 4, h = bh & 15;

    const int ldr = tid >> 1;            // row this thread loads (2 thr/row)
    const int ldc = (tid & 1) * 8;       // base float4-quad within row

    // ---- Q tile once, raw padded rows ----
    {
        const float4* Qg = (const float4*)(Q + ((size_t)bh * L + qt * 128) * D);
        #pragma unroll
        for (int it = 0; it < 8; it++) {
            int i = tid + it * 256; int r = i >> 4, dq = i & 15;
            ((float4*)(Qs + r * SQ))[dq] = Qg[r * 16 + dq];
        }
    }

    const float* Kgb = K + (size_t)bh * L * D;

    // prologue: start K(0)
    {
        const float* Kg = Kgb;           // kt = 0
        #pragma unroll
        for (int q = 0; q < 8; q++)
            cp16(Ksb + ldr * SQ + (ldc + q) * 4, Kg + ldr * 64 + (ldc + q) * 4);
        cp_commit();
    }

    float l_run[4] = {0.f, 0.f, 0.f, 0.f};

    for (int kt = 0; kt < 8; kt++) {
        __syncthreads();   // prior MMA done reading the buffer we now overwrite
        if (kt < 7) {
            float* Kn = Ksb + ((kt + 1) & 1) * 128 * SQ;
            const float* Kg = Kgb + (size_t)(kt + 1) * 128 * D;
            #pragma unroll
            for (int q = 0; q < 8; q++)
                cp16(Kn + ldr * SQ + (ldc + q) * 4, Kg + ldr * 64 + (ldc + q) * 4);
            cp_commit();
            cp_wait<1>();      // K(kt) landed (K(kt+1) still in flight)
        } else {
            cp_wait<0>();
        }
        __syncthreads();   // K(kt) visible block-wide

        float acc[2][8][4];
        #pragma unroll
        for (int mt = 0; mt < 2; mt++)
            #pragma unroll
            for (int nt = 0; nt < 8; nt++)
                #pragma unroll
                for (int r = 0; r < 4; r++) acc[mt][nt][r] = 0.f;

        const float* Qw = Qs + (wq * 32) * SQ;
        const float* Kw = Ksb + (kt & 1) * 128 * SQ + (wk * 64) * SQ;

        #pragma unroll
        for (int kk = 0; kk < 8; kk++) {
            uint32_t ahi[2][4], alo[2][4];
            #pragma unroll
            for (int mt = 0; mt < 2; mt++)
                #pragma unroll
                for (int r = 0; r < 4; r++) {
                    int row = mt * 16 + g + (r & 1) * 8;
                    int col = kk * 8 + t + (r >> 1) * 4;
                    float x = Qw[row * SQ + col];
                    uint32_t hi = f2tf(x);
                    ahi[mt][r] = hi;
                    alo[mt][r] = f2tf(x - __uint_as_float(hi));
                }
            #pragma unroll
            for (int nt = 0; nt < 8; nt++) {
                uint32_t bhi[2], blo[2];
                #pragma unroll
                for (int r = 0; r < 2; r++) {
                    float x = Kw[(nt * 8 + g) * SQ + kk * 8 + t + r * 4];
                    uint32_t hi = f2tf(x);
                    bhi[r] = hi;
                    blo[r] = f2tf(x - __uint_as_float(hi));
                }
                #pragma unroll
                for (int mt = 0; mt < 2; mt++) {
                    mma_tf32(acc[mt][nt], ahi[mt][0], ahi[mt][1], ahi[mt][2], ahi[mt][3], blo[0], blo[1]);
                    mma_tf32(acc[mt][nt], alo[mt][0], alo[mt][1], alo[mt][2], alo[mt][3], bhi[0], bhi[1]);
                    mma_tf32(acc[mt][nt], ahi[mt][0], ahi[mt][1], ahi[mt][2], ahi[mt][3], bhi[0], bhi[1]);
                }
            }
        }

        // ---- epilogue: scale, mask, bias, store e=exp(s), accumulate l ----
        const int q0 = qt * 128 + wq * 32;
        const int cp0 = kt * 64 + wk * 32;   // float2 col-index base
        #pragma unroll
        for (int mt = 0; mt < 2; mt++)
            #pragma unroll
            for (int half = 0; half < 2; half++) {
                int row = q0 + mt * 16 + half * 8 + g;
                const int2*   mrow = (const int2*)  (mask  + ((size_t)b  * L + row) * L);
                const float2* brow = (const float2*)(bias  + ((size_t)h  * L + row) * L);
                float2*       srow = (float2*)      (score + ((size_t)bh * L + row) * L);
                float lsum = 0.f;
                #pragma unroll
                for (int nt = 0; nt < 8; nt++) {
                    int cp = cp0 + nt * 4 + t;
                    int2   mv = mrow[cp];
                    float2 bv = brow[cp];
                    float s0 = acc[mt][nt][half * 2 + 0] * 0.125f;
                    float s1 = acc[mt][nt][half * 2 + 1] * 0.125f;
                    s0 = (mv.x == 0 ? -10000.f : s0) + bv.x;
                    s1 = (mv.y == 0 ? -10000.f : s1) + bv.y;
                    float e0 = __expf(s0), e1 = __expf(s1);
                    srow[cp] = make_float2(e0, e1);
                    lsum += e0 + e1;
                }
                l_run[mt * 2 + half] += lsum;
            }
    }

    // reduce l over the 4 t-lanes, then across the 2 wk groups
    #pragma unroll
    for (int li = 0; li < 4; li++) {
        l_run[li] += __shfl_xor_sync(0xffffffffu, l_run[li], 1);
        l_run[li] += __shfl_xor_sync(0xffffffffu, l_run[li], 2);
    }
    __syncthreads();
    if (t == 0) {
        #pragma unroll
        for (int li = 0; li < 4; li++) {
            int row = wq * 32 + (li >> 1) * 16 + (li & 1) * 8 + g;
            sred[wk * 128 + row] = l_run[li];
        }
    }
    __syncthreads();
    if (tid < 128) {
        float l = sred[tid] + sred[128 + tid];
        g_inv_l[(size_t)bh * L + qt * 128 + tid] = 1.0f / l;
    }
}

// ---------------------------------------------------------------------------
// Kernel 2 (R4, measured 191us): O = P V with P = e * inv_l; writes normalized
// p over e in score. Fragment-major pre-converted tf32 smem; register-staged
// software pipeline over 16 k-chunks of 64.
// ---------------------------------------------------------------------------
struct Stage { float4 se[8]; float4 sv[4]; };

__device__ __forceinline__ void load_stage(Stage& st, const float* sbase,
                                           const float4* Vg, int c, int tid)
{
    const int prow = tid >> 1;
    #pragma unroll
    for (int it = 0; it < 8; it++) {
        int qcol = (tid & 1) + it * 2;
        st.se[it] = *(const float4*)(sbase + (size_t)prow * L + c * 64 + qcol * 4);
    }
    const int vrow = tid >> 2;
    #pragma unroll
    for (int it = 0; it < 4; it++) {
        int qd = (tid & 3) + it * 4;
        st.sv[it] = Vg[(size_t)(c * 64 + vrow) * 16 + qd];
    }
}

__global__ __launch_bounds__(256, 2)
void pv_kernel(const float* __restrict__ V, float* score, float* __restrict__ out)
{
    extern __shared__ uint32_t smu[];
    uint32_t* AF   = smu;                    // 8192 uints (32 KB): P fragments tf32
    uint32_t* VF   = smu + 8192;             // 4096 uints (16 KB): V fragments tf32
    float*    sinv = (float*)(smu + 8192 + 4096);   // 128 floats

    const int tid  = threadIdx.x;
    const int lane = tid & 31, wid = tid >> 5;
    const int g = lane >> 2, t = lane & 3;
    const int qt = blockIdx.x, bh = blockIdx.y;

    const float4* Vg    = (const float4*)(V + (size_t)bh * L * D);
    float*        sbase = score + ((size_t)bh * L + qt * 128) * L;

    Stage st;
    load_stage(st, sbase, Vg, 0, tid);
    if (tid < 128) sinv[tid] = g_inv_l[(size_t)bh * L + qt * 128 + tid];
    __syncthreads();
    const float il = sinv[tid >> 1];

    float acc[8][4];
    #pragma unroll
    for (int nt = 0; nt < 8; nt++)
        #pragma unroll
        for (int r = 0; r < 4; r++) acc[nt][r] = 0.f;

    // per-thread constant scatter indices
    const int prow = tid >> 1;
    const int wqr = prow >> 4, gp = prow & 15, gg = gp & 7, rlo = gp >> 3;
    const int vrow = tid >> 2;
    const int vkk = vrow >> 3, ts = vrow & 7, vword = ts >> 2, vt = ts & 3;

    for (int c = 0; c < 16; c++) {
        __syncthreads();   // previous MMA done reading smem
        // ---- transform + store stage: p = e*il -> gmem + fragment smem ----
        #pragma unroll
        for (int it = 0; it < 8; it++) {
            int qcol = (tid & 1) + it * 2;
            float4 p;
            p.x = st.se[it].x * il; p.y = st.se[it].y * il;
            p.z = st.se[it].z * il; p.w = st.se[it].w * il;
            *(float4*)(sbase + (size_t)prow * L + c * 64 + qcol * 4) = p;
            int kk = qcol >> 1, r = ((qcol & 1) << 1) | rlo;
            uint32_t* dst = AF + (wqr * 8 + kk) * 128 + r;
            dst[(gg * 4 + 0) * 4] = f2tf(p.x);
            dst[(gg * 4 + 1) * 4] = f2tf(p.y);
            dst[(gg * 4 + 2) * 4] = f2tf(p.z);
            dst[(gg * 4 + 3) * 4] = f2tf(p.w);
        }
        #pragma unroll
        for (int it = 0; it < 4; it++) {
            int qd = (tid & 3) + it * 4;
            #pragma unroll
            for (int j = 0; j < 4; j++) {
                int n = qd * 4 + j;
                int nt = n >> 3, gn = n & 7;
                VF[((vkk * 8 + nt) * 32 + gn * 4 + vt) * 2 + vword] = f2tf((&st.sv[it].x)[j]);
            }
        }
        __syncthreads();

        if (c < 15) load_stage(st, sbase, Vg, c + 1, tid);   // overlap with MMA

        const uint4* AF4 = (const uint4*)AF;
        const uint2* VF2 = (const uint2*)VF;
        #pragma unroll
        for (int kk = 0; kk < 8; kk++) {
            uint4 a = AF4[(wid * 8 + kk) * 32 + lane];
            #pragma unroll
            for (int nt = 0; nt < 8; nt++) {
                uint2 bb = VF2[(kk * 8 + nt) * 32 + lane];
                mma_tf32(acc[nt], a.x, a.y, a.z, a.w, bb.x, bb.y);
            }
        }
    }

    #pragma unroll
    for (int half = 0; half < 2; half++) {
        int row = qt * 128 + wid * 16 + half * 8 + g;
        float2* orow = (float2*)(out + ((size_t)bh * L + row) * D);
        #pragma unroll
        for (int nt = 0; nt < 8; nt++)
            orow[nt * 4 + t] = make_float2(acc[nt][half * 2], acc[nt][half * 2 + 1]);
    }
}

// ---------------------------------------------------------------------------
extern "C" void kernel_launch(void* const* d_in, const int* in_sizes, int n_in,
                              void* d_out, int out_size)
{
    const float* Q    = (const float*)d_in[0];
    const float* K    = (const float*)d_in[1];
    const float* V    = (const float*)d_in[2];
    const int*   mask = (const int*)  d_in[3];
    const float* bias = (const float*)d_in[4];

    float* out   = (float*)d_out;
    float* score = out + OUT_ELEMS;   // tuple order: (out, score)

    const int qk_smem = (3 * 128 * SQ + 256) * 4;    // 105472 B
    const int pv_smem = (8192 + 4096 + 128) * 4;     // 49664 B
    cudaFuncSetAttribute(qks_kernel, cudaFuncAttributeMaxDynamicSharedMemorySize, qk_smem);
    cudaFuncSetAttribute(pv_kernel,  cudaFuncAttributeMaxDynamicSharedMemorySize, pv_smem);

    qks_kernel<<<dim3(8, 64), 256, qk_smem>>>(Q, K, mask, bias, score);
    pv_kernel <<<dim3(8, 64), 256, pv_smem>>>(V, score, out);
}

// round 13
// speedup vs baseline: 1.4569x; 1.1395x over previous
#include <cuda_runtime.h>
#include <cstdint>

#define L 1024
#define D 64
#define NBH 64
#define OUT_ELEMS (NBH*L*D)
#define SQ 68   // padded row stride (floats) for Q/K smem

__device__ float g_inv_l[NBH * L];   // per-row 1/sum(exp(s)), qk -> pv

__device__ __forceinline__ uint32_t f2tf(float x) {
    uint32_t r; asm("cvt.rna.tf32.f32 %0, %1;" : "=r"(r) : "f"(x)); return r;
}

__device__ __forceinline__ void mma_tf32(float* c,
    uint32_t a0, uint32_t a1, uint32_t a2, uint32_t a3, uint32_t b0, uint32_t b1)
{
    asm("mma.sync.aligned.m16n8k8.row.col.f32.tf32.tf32.f32 "
        "{%0,%1,%2,%3}, {%4,%5,%6,%7}, {%8,%9}, {%0,%1,%2,%3};"
        : "+f"(c[0]), "+f"(c[1]), "+f"(c[2]), "+f"(c[3])
        : "r"(a0), "r"(a1), "r"(a2), "r"(a3), "r"(b0), "r"(b1));
}

// ---------------------------------------------------------------------------
// Kernel 1 (R3 structure verbatim, 229us measured; epilogue stores e=exp(s)).
// Per (qt, bh) strip of 128 x 1024:
// e = exp(QK^T/8 masked + bias) -> score buffer (holds exp!), and
// g_inv_l = 1 / row-sum(e).  3xTF32 split MMA, raw padded-row smem,
// in-loop hi/lo tf32 split. Smem 70656 B -> 2 CTAs/SM + 86 KB L1.
// ---------------------------------------------------------------------------
__global__ __launch_bounds__(256, 2)
void qks_kernel(const float* __restrict__ Q, const float* __restrict__ K,
                const int* __restrict__ mask, const float* __restrict__ bias,
                float* __restrict__ score)
{
    extern __shared__ float sm[];
    float* Qs   = sm;                 // 128 x 68
    float* Ks   = sm + 128 * SQ;      // 128 x 68
    float* sred = sm + 2 * 128 * SQ;  // 2 x 128

    const int tid  = threadIdx.x;
    const int lane = tid & 31, wid = tid >> 5;
    const int wq = wid & 3, wk = wid >> 2;
    const int g = lane >> 2, t = lane & 3;
    const int qt = blockIdx.x, bh = blockIdx.y;
    const int b = bh >> 4, h = bh & 15;

    // load Q tile (stays for whole strip)
    {
        const float4* Qg = (const float4*)(Q + ((size_t)bh * L + qt * 128) * D);
        #pragma unroll
        for (int it = 0; it < 8; it++) {
            int i = tid + it * 256; int r = i >> 4, dq = i & 15;
            ((float4*)(Qs + r * SQ))[dq] = Qg[r * 16 + dq];
        }
    }

    float l_run[4] = {0.f, 0.f, 0.f, 0.f};

    for (int kt = 0; kt < 8; kt++) {
        __syncthreads();
        {
            const float4* Kg = (const float4*)(K + ((size_t)bh * L + kt * 128) * D);
            #pragma unroll
            for (int it = 0; it < 8; it++) {
                int i = tid + it * 256; int r = i >> 4, dq = i & 15;
                ((float4*)(Ks + r * SQ))[dq] = Kg[r * 16 + dq];
            }
        }
        __syncthreads();

        float acc[2][8][4];
        #pragma unroll
        for (int mt = 0; mt < 2; mt++)
            #pragma unroll
            for (int nt = 0; nt < 8; nt++)
                #pragma unroll
                for (int r = 0; r < 4; r++) acc[mt][nt][r] = 0.f;

        const float* Qw = Qs + (wq * 32) * SQ;
        const float* Kw = Ks + (wk * 64) * SQ;

        #pragma unroll
        for (int kk = 0; kk < 8; kk++) {
            uint32_t ahi[2][4], alo[2][4];
            #pragma unroll
            for (int mt = 0; mt < 2; mt++)
                #pragma unroll
                for (int r = 0; r < 4; r++) {
                    int row = mt * 16 + g + (r & 1) * 8;
                    int col = kk * 8 + t + (r >> 1) * 4;
                    float x = Qw[row * SQ + col];
                    uint32_t hi = f2tf(x);
                    ahi[mt][r] = hi;
                    alo[mt][r] = f2tf(x - __uint_as_float(hi));
                }
            #pragma unroll
            for (int nt = 0; nt < 8; nt++) {
                uint32_t bhi[2], blo[2];
                #pragma unroll
                for (int r = 0; r < 2; r++) {
                    float x = Kw[(nt * 8 + g) * SQ + kk * 8 + t + r * 4];
                    uint32_t hi = f2tf(x);
                    bhi[r] = hi;
                    blo[r] = f2tf(x - __uint_as_float(hi));
                }
                #pragma unroll
                for (int mt = 0; mt < 2; mt++) {
                    mma_tf32(acc[mt][nt], ahi[mt][0], ahi[mt][1], ahi[mt][2], ahi[mt][3], blo[0], blo[1]);
                    mma_tf32(acc[mt][nt], alo[mt][0], alo[mt][1], alo[mt][2], alo[mt][3], bhi[0], bhi[1]);
                    mma_tf32(acc[mt][nt], ahi[mt][0], ahi[mt][1], ahi[mt][2], ahi[mt][3], bhi[0], bhi[1]);
                }
            }
        }

        // epilogue: scale, mask, bias, store e=exp(s), accumulate l
        const int q0 = qt * 128 + wq * 32;
        const int cp0 = kt * 64 + wk * 32;   // float2 col-index base
        #pragma unroll
        for (int mt = 0; mt < 2; mt++)
            #pragma unroll
            for (int half = 0; half < 2; half++) {
                int row = q0 + mt * 16 + half * 8 + g;
                const int2*   mrow = (const int2*)  (mask  + ((size_t)b  * L + row) * L);
                const float2* brow = (const float2*)(bias  + ((size_t)h  * L + row) * L);
                float2*       srow = (float2*)      (score + ((size_t)bh * L + row) * L);
                float lsum = 0.f;
                #pragma unroll
                for (int nt = 0; nt < 8; nt++) {
                    int cp = cp0 + nt * 4 + t;
                    int2   mv = mrow[cp];
                    float2 bv = brow[cp];
                    float s0 = acc[mt][nt][half * 2 + 0] * 0.125f;
                    float s1 = acc[mt][nt][half * 2 + 1] * 0.125f;
                    s0 = (mv.x == 0 ? -10000.f : s0) + bv.x;
                    s1 = (mv.y == 0 ? -10000.f : s1) + bv.y;
                    float e0 = __expf(s0), e1 = __expf(s1);
                    srow[cp] = make_float2(e0, e1);
                    lsum += e0 + e1;
                }
                l_run[mt * 2 + half] += lsum;
            }
    }

    #pragma unroll
    for (int li = 0; li < 4; li++) {
        l_run[li] += __shfl_xor_sync(0xffffffffu, l_run[li], 1);
        l_run[li] += __shfl_xor_sync(0xffffffffu, l_run[li], 2);
    }
    __syncthreads();
    if (t == 0) {
        #pragma unroll
        for (int li = 0; li < 4; li++) {
            int row = wq * 32 + (li >> 1) * 16 + (li & 1) * 8 + g;
            sred[wk * 128 + row] = l_run[li];
        }
    }
    __syncthreads();
    if (tid < 128) {
        float l = sred[tid] + sred[128 + tid];
        g_inv_l[(size_t)bh * L + qt * 128 + tid] = 1.0f / l;
    }
}

// ---------------------------------------------------------------------------
// Kernel 2 (R4 structure + double-buffered smem, 1 sync/chunk):
// O = P V with P = e * inv_l; writes normalized p over e in score.
// Fragment-major pre-converted tf32 smem; register-staged pipeline.
// ---------------------------------------------------------------------------
#define PVBUF 12288   // uints per buffer: AF 8192 + VF 4096

struct Stage { float4 se[8]; float4 sv[4]; };

__device__ __forceinline__ void load_stage(Stage& st, const float* sbase,
                                           const float4* Vg, int c, int tid)
{
    const int prow = tid >> 1;
    #pragma unroll
    for (int it = 0; it < 8; it++) {
        int qcol = (tid & 1) + it * 2;
        st.se[it] = *(const float4*)(sbase + (size_t)prow * L + c * 64 + qcol * 4);
    }
    const int vrow = tid >> 2;
    #pragma unroll
    for (int it = 0; it < 4; it++) {
        int qd = (tid & 3) + it * 4;
        st.sv[it] = Vg[(size_t)(c * 64 + vrow) * 16 + qd];
    }
}

__global__ __launch_bounds__(256, 2)
void pv_kernel(const float* __restrict__ V, float* score, float* __restrict__ out)
{
    extern __shared__ uint32_t smu[];
    // two buffers of {AF[8192], VF[4096]}, then sinv
    float* sinv = (float*)(smu + 2 * PVBUF);   // 128 floats

    const int tid  = threadIdx.x;
    const int lane = tid & 31, wid = tid >> 5;
    const int g = lane >> 2, t = lane & 3;
    const int qt = blockIdx.x, bh = blockIdx.y;

    const float4* Vg    = (const float4*)(V + (size_t)bh * L * D);
    float*        sbase = score + ((size_t)bh * L + qt * 128) * L;

    Stage st;
    load_stage(st, sbase, Vg, 0, tid);
    if (tid < 128) sinv[tid] = g_inv_l[(size_t)bh * L + qt * 128 + tid];
    __syncthreads();
    const float il = sinv[tid >> 1];

    float acc[8][4];
    #pragma unroll
    for (int nt = 0; nt < 8; nt++)
        #pragma unroll
        for (int r = 0; r < 4; r++) acc[nt][r] = 0.f;

    // per-thread constant scatter indices
    const int prow = tid >> 1;
    const int wqr = prow >> 4, gp = prow & 15, gg = gp & 7, rlo = gp >> 3;
    const int vrow = tid >> 2;
    const int vkk = vrow >> 3, ts = vrow & 7, vword = ts >> 2, vt = ts & 3;

    for (int c = 0; c < 16; c++) {
        uint32_t* AF = smu + (c & 1) * PVBUF;
        uint32_t* VF = AF + 8192;

        // ---- transform + store stage: p = e*il -> gmem + fragment smem ----
        #pragma unroll
        for (int it = 0; it < 8; it++) {
            int qcol = (tid & 1) + it * 2;
            float4 p;
            p.x = st.se[it].x * il; p.y = st.se[it].y * il;
            p.z = st.se[it].z * il; p.w = st.se[it].w * il;
            *(float4*)(sbase + (size_t)prow * L + c * 64 + qcol * 4) = p;
            int kk = qcol >> 1, r = ((qcol & 1) << 1) | rlo;
            uint32_t* dst = AF + (wqr * 8 + kk) * 128 + r;
            dst[(gg * 4 + 0) * 4] = f2tf(p.x);
            dst[(gg * 4 + 1) * 4] = f2tf(p.y);
            dst[(gg * 4 + 2) * 4] = f2tf(p.z);
            dst[(gg * 4 + 3) * 4] = f2tf(p.w);
        }
        #pragma unroll
        for (int it = 0; it < 4; it++) {
            int qd = (tid & 3) + it * 4;
            #pragma unroll
            for (int j = 0; j < 4; j++) {
                int n = qd * 4 + j;
                int nt = n >> 3, gn = n & 7;
                VF[((vkk * 8 + nt) * 32 + gn * 4 + vt) * 2 + vword] = f2tf((&st.sv[it].x)[j]);
            }
        }
        __syncthreads();   // buf[c&1] ready; all warps past MMA(c-1)

        if (c < 15) load_stage(st, sbase, Vg, c + 1, tid);   // overlap with MMA

        const uint4* AF4 = (const uint4*)AF;
        const uint2* VF2 = (const uint2*)(AF + 8192);
        #pragma unroll
        for (int kk = 0; kk < 8; kk++) {
            uint4 a = AF4[(wid * 8 + kk) * 32 + lane];
            #pragma unroll
            for (int nt = 0; nt < 8; nt++) {
                uint2 bb = VF2[(kk * 8 + nt) * 32 + lane];
                mma_tf32(acc[nt], a.x, a.y, a.z, a.w, bb.x, bb.y);
            }
        }
        // no second sync: next iteration writes the other buffer; the single
        // sync above guarantees MMA(c-1) (last reader of that buffer) is done.
    }

    #pragma unroll
    for (int half = 0; half < 2; half++) {
        int row = qt * 128 + wid * 16 + half * 8 + g;
        float2* orow = (float2*)(out + ((size_t)bh * L + row) * D);
        #pragma unroll
        for (int nt = 0; nt < 8; nt++)
            orow[nt * 4 + t] = make_float2(acc[nt][half * 2], acc[nt][half * 2 + 1]);
    }
}

// ---------------------------------------------------------------------------
extern "C" void kernel_launch(void* const* d_in, const int* in_sizes, int n_in,
                              void* d_out, int out_size)
{
    const float* Q    = (const float*)d_in[0];
    const float* K    = (const float*)d_in[1];
    const float* V    = (const float*)d_in[2];
    const int*   mask = (const int*)  d_in[3];
    const float* bias = (const float*)d_in[4];

    float* out   = (float*)d_out;
    float* score = out + OUT_ELEMS;   // tuple order: (out, score)

    const int qk_smem = (2 * 128 * SQ + 256) * 4;        // 70656 B
    const int pv_smem = (2 * PVBUF + 128) * 4;           // 98816 B
    cudaFuncSetAttribute(qks_kernel, cudaFuncAttributeMaxDynamicSharedMemorySize, qk_smem);
    cudaFuncSetAttribute(pv_kernel,  cudaFuncAttributeMaxDynamicSharedMemorySize, pv_smem);

    qks_kernel<<<dim3(8, 64), 256, qk_smem>>>(Q, K, mask, bias, score);
    pv_kernel <<<dim3(8, 64), 256, pv_smem>>>(V, score, out);
}